// round 16
// baseline (speedup 1.0000x reference)
#include <cuda_runtime.h>
#include <cstdint>

#define BSZ 2
#define NN  4096
#define JJ  3
#define CC  32
#define KO  32
#define MJ  (NN*JJ)               // 12288
#define BM  256
#define BKT 96
#define NTILES (NN/BM)            // 16
#define CHUNKS (MJ/BKT)           // 128
#define TOTAL_STEPS (BSZ*NTILES*CHUNKS)   // 4096
#define NBLK 148                  // one persistent block per SM
#define WST 40                    // t stride: b-frag banks conflict-free
#define W_WORDS (BM*BKT)                      // 24576 (swizzled, no padding)
#define T_WORDS (BKT*WST)                     // 3840
#define STAGE_WORDS (W_WORDS + T_WORDS)       // 28416
#define GEMM_SMEM (2 * STAGE_WORDS * 4)       // 227328 B

__device__ float g_t[BSZ * MJ * KO];          // t[b][mj][k] (tf32 bits)

__device__ __forceinline__ uint32_t f2tf32(float f) {
    uint32_t o;
    asm("cvt.rna.tf32.f32 %0, %1;" : "=r"(o) : "f"(f));
    return o;
}

// ---------------------------------------------------------------------------
// Fused: out init + t[bm][j*32+k] = (1+2^-11)*sum_c cw*x.  1024 blocks x 8 rows.
// ---------------------------------------------------------------------------
__global__ __launch_bounds__(256) void precompute_t_kernel(const float* __restrict__ x,
                                                           const float* __restrict__ cw,
                                                           float* __restrict__ out,
                                                           const float* __restrict__ cb) {
    __shared__ float cws[KO * 100];
    __shared__ float xs[8 * 36];

    const int tid = threadIdx.x;
    const int bm0 = blockIdx.x * 8;

    {   // out init: 256 elements per block
        int idx = blockIdx.x * 256 + tid;
        out[idx] = cb[(idx >> 12) & 31];
    }

#pragma unroll
    for (int p = 0; p < 3; ++p) {
        int idx = p * 256 + tid;               // 768 float4 of conv_w
        int r = idx / 24, cv = idx % 24;
        float4 v = ((const float4*)cw)[idx];
        *(float4*)(cws + r * 100 + cv * 4) = v;
    }
    if (tid < 64) {                            // 8x32 = 64 float4 of x
        int r = tid >> 3, cv = tid & 7;
        float4 v = ((const float4*)(x + (size_t)bm0 * CC))[tid];
        *(float4*)(xs + r * 36 + cv * 4) = v;
    }
    __syncthreads();

#pragma unroll
    for (int p = 0; p < 3; ++p) {
        int o = p * 256 + tid;                 // 0..767
        int bm = o / 96, jk = o % 96;
        int j = jk >> 5, k = jk & 31;
        const float* xr = xs + bm * 36;
        const float* wr = cws + k * 100 + j * 32;
        float s = 0.f;
#pragma unroll
        for (int cv = 0; cv < 8; ++cv) {
            float4 xv = *(const float4*)(xr + cv * 4);
            float4 wv = *(const float4*)(wr + cv * 4);
            s = fmaf(xv.x, wv.x, s);
            s = fmaf(xv.y, wv.y, s);
            s = fmaf(xv.z, wv.z, s);
            s = fmaf(xv.w, wv.w, s);
        }
        s *= (1.0f + 4.8828125e-4f);           // cancel tf32 truncation bias on W
        ((uint32_t*)g_t)[(size_t)bm0 * 96 + o] = f2tf32(s);
    }
}

// ---------------------------------------------------------------------------
// Balanced persistent split-K tf32 GEMM. BKT=96 (384 B/row bursts), XOR-
// swizzled W tile, 2-stage double buffer. 8 warps x 32 rows.
// ---------------------------------------------------------------------------
extern __shared__ uint32_t smem_dyn[];

__global__ __launch_bounds__(256, 1) void gemm_kernel(const float* __restrict__ W,
                                                      float* __restrict__ out) {
    const int tid  = threadIdx.x;
    const int warp = tid >> 5, lane = tid & 31;
    const int lg   = lane >> 2, lt = lane & 3;
    const int row0 = warp * 32;
    const int swz  = lg << 2;              // a-frag swizzle (row&7 == lg)

    int s0 = (int)(((long long)blockIdx.x * TOTAL_STEPS) / NBLK);
    const int s_end = (int)(((long long)(blockIdx.x + 1) * TOTAL_STEPS) / NBLK);

    while (s0 < s_end) {
        const int tile = s0 / CHUNKS;
        const int seg_end = min(s_end, (tile + 1) * CHUNKS);
        const int len = seg_end - s0;
        const int b  = tile >> 4;
        const int n0 = (tile & 15) * BM;
        const int kk0 = (s0 - tile * CHUNKS) * BKT;

        const float* Wbase = W   + ((size_t)(b * NN + n0)) * MJ + kk0;
        const float* Tbase = g_t + ((size_t)b * MJ + kk0) * KO;

        float acc[2][4][4];
#pragma unroll
        for (int m = 0; m < 2; ++m)
#pragma unroll
            for (int i = 0; i < 4; ++i)
#pragma unroll
                for (int j = 0; j < 4; ++j) acc[m][i][j] = 0.f;

#define FILL(s, t)                                                                \
    {                                                                             \
        uint32_t* Wst = smem_dyn + (s) * STAGE_WORDS;                             \
        uint32_t* Tst = Wst + W_WORDS;                                            \
        const float* wp_ = Wbase + (t) * BKT;                                     \
        _Pragma("unroll")                                                         \
        for (int q = 0; q < 24; ++q) {                                            \
            int idx_ = q * 256 + tid;                                             \
            int r_ = idx_ / 24;                                                   \
            int c_ = (idx_ % 24) * 4;                                             \
            uint32_t d_ = (uint32_t)__cvta_generic_to_shared(                     \
                &Wst[r_ * BKT + (c_ ^ ((r_ & 7) << 2))]);                         \
            asm volatile("cp.async.cg.shared.global [%0], [%1], 16;" ::           \
                         "r"(d_), "l"(wp_ + (size_t)r_ * MJ + c_));               \
        }                                                                         \
        _Pragma("unroll")                                                         \
        for (int q = 0; q < 3; ++q) {                                             \
            int idx_ = q * 256 + tid;                                             \
            int kk_ = idx_ >> 3;                                                  \
            int ko_ = (idx_ & 7) * 4;                                             \
            uint32_t d_ = (uint32_t)__cvta_generic_to_shared(                     \
                &Tst[kk_ * WST + ko_]);                                           \
            asm volatile("cp.async.cg.shared.global [%0], [%1], 16;" ::           \
                         "r"(d_), "l"(Tbase + ((size_t)(t) * BKT + kk_) * KO + ko_)); \
        }                                                                         \
    }

        // prefill both stages
        if (0 < len) FILL(0, 0);
        asm volatile("cp.async.commit_group;");
        if (1 < len) FILL(1, 1);
        asm volatile("cp.async.commit_group;");

        for (int it = 0; it < len; ++it) {
            asm volatile("cp.async.wait_group 1;");   // tile it landed (this thread)
            __syncthreads();                          // landed for all threads

            const uint32_t* Ws = smem_dyn + (it & 1) * STAGE_WORDS;
            const uint32_t* Ts = Ws + W_WORDS;
#pragma unroll
            for (int s4 = 0; s4 < 12; ++s4) {
                const int kc = s4 * 8;
                const int c0 = (kc + lt) ^ swz;
                const int c1 = (kc + lt + 4) ^ swz;
                uint32_t a[2][4];
#pragma unroll
                for (int m = 0; m < 2; ++m) {
                    int r = row0 + m * 16 + lg;
                    a[m][0] = Ws[r * BKT + c0];
                    a[m][1] = Ws[(r + 8) * BKT + c0];
                    a[m][2] = Ws[r * BKT + c1];
                    a[m][3] = Ws[(r + 8) * BKT + c1];
                }
#pragma unroll
                for (int nt = 0; nt < 4; ++nt) {
                    uint32_t b0 = Ts[(kc + lt)     * WST + nt * 8 + lg];
                    uint32_t b1 = Ts[(kc + lt + 4) * WST + nt * 8 + lg];
#pragma unroll
                    for (int m = 0; m < 2; ++m) {
                        asm volatile(
                            "mma.sync.aligned.m16n8k8.row.col.f32.tf32.tf32.f32 "
                            "{%0,%1,%2,%3}, {%4,%5,%6,%7}, {%8,%9}, {%0,%1,%2,%3};"
                            : "+f"(acc[m][nt][0]), "+f"(acc[m][nt][1]),
                              "+f"(acc[m][nt][2]), "+f"(acc[m][nt][3])
                            : "r"(a[m][0]), "r"(a[m][1]), "r"(a[m][2]), "r"(a[m][3]),
                              "r"(b0), "r"(b1));
                    }
                }
            }

            __syncthreads();                          // stage it&1 free to refill
            if (it + 2 < len) FILL(it & 1, it + 2);
            asm volatile("cp.async.commit_group;");
        }
#undef FILL

        // ---- flush segment: stage 256x32 in smem (stride 33), coalesced REDG ----
        asm volatile("cp.async.wait_group 0;");
        __syncthreads();
        float* stg = (float*)smem_dyn;                // 33.8 KB
#pragma unroll
        for (int m = 0; m < 2; ++m)
#pragma unroll
            for (int nt = 0; nt < 4; ++nt) {
                int col = nt * 8 + lt * 2;
                int r = row0 + m * 16 + lg;
                stg[r * 33 + col]           = acc[m][nt][0];
                stg[r * 33 + col + 1]       = acc[m][nt][1];
                stg[(r + 8) * 33 + col]     = acc[m][nt][2];
                stg[(r + 8) * 33 + col + 1] = acc[m][nt][3];
            }
        __syncthreads();
        float* obase = out + (size_t)b * (KO * NN);
#pragma unroll
        for (int p = 0; p < 32; ++p) {
            int idx = p * 256 + tid;           // 8192 outputs
            int nl = idx & 255, k = idx >> 8;
            atomicAdd(obase + (size_t)k * NN + n0 + nl, stg[nl * 33 + k]);
        }
        __syncthreads();                        // staging freed before next FILL

        s0 = seg_end;
    }
}

// ---------------------------------------------------------------------------
extern "C" void kernel_launch(void* const* d_in, const int* in_sizes, int n_in,
                              void* d_out, int out_size) {
    const float* W  = (const float*)d_in[0];
    const float* x  = (const float*)d_in[1];
    const float* cw = (const float*)d_in[2];
    const float* cb = (const float*)d_in[3];
    float* out = (float*)d_out;

    static int attr_set = 0;
    if (!attr_set) {
        cudaFuncSetAttribute(gemm_kernel,
                             cudaFuncAttributeMaxDynamicSharedMemorySize, GEMM_SMEM);
        attr_set = 1;
    }

    precompute_t_kernel<<<(BSZ * NN) / 8, 256>>>(x, cw, out, cb);
    gemm_kernel<<<NBLK, 256, GEMM_SMEM>>>(W, out);
}